// round 8
// baseline (speedup 1.0000x reference)
#include <cuda_runtime.h>
#include <cstdint>

#define BATCH  4
#define N_PTS  16384
#define N_SAMP 1024
#define K_NEI  32
#define C_FEAT 128
#define CL     8               // cluster size (CTAs per batch)
#define TPB    128
#define NWARP  (TPB / 32)      // 4 warps per CTA
#define PPT    16              // N_PTS / (CL*TPB)
#define NPAIR  (PPT / 2)
#define NSLOT  (CL * NWARP)    // 32 cluster-wide warp candidates (== warp size)
#define FULL   0xffffffffu
#define TX_BYTES (NSLOT * 16u) // 32 producers x one v4 (16B)

// scratch: neighbor indices (device global -> no allocation)
__device__ int g_nidx[BATCH * N_SAMP * K_NEI];

// ---------------- f32x2 packed helpers (per-lane IEEE .rn == scalar) ----------------
__device__ __forceinline__ uint64_t pack2(float lo, float hi) {
    uint64_t r;
    asm("mov.b64 %0, {%1, %2};" : "=l"(r) : "f"(lo), "f"(hi));
    return r;
}
__device__ __forceinline__ void unpack2(uint64_t v, float& lo, float& hi) {
    asm("mov.b64 {%0, %1}, %2;" : "=f"(lo), "=f"(hi) : "l"(v));
}
__device__ __forceinline__ uint64_t add2(uint64_t a, uint64_t b) {
    uint64_t r;
    asm("add.rn.f32x2 %0, %1, %2;" : "=l"(r) : "l"(a), "l"(b));
    return r;
}
__device__ __forceinline__ uint64_t mul2(uint64_t a, uint64_t b) {
    uint64_t r;
    asm("mul.rn.f32x2 %0, %1, %2;" : "=l"(r) : "l"(a), "l"(b));
    return r;
}

// ---------------- threefry2x32 (JAX-compatible, both output words) ----------------
__device__ __forceinline__ uint32_t rotl32(uint32_t x, int r) {
    return (x << r) | (x >> (32 - r));
}

__device__ __forceinline__ void threefry2x32(uint32_t k0, uint32_t k1,
                                             uint32_t x0, uint32_t x1,
                                             uint32_t& o0, uint32_t& o1) {
    uint32_t ks2 = k0 ^ k1 ^ 0x1BD11BDAu;
    x0 += k0; x1 += k1;
#define TF_RND(r) { x0 += x1; x1 = rotl32(x1, (r)); x1 ^= x0; }
    TF_RND(13) TF_RND(15) TF_RND(26) TF_RND(6)   x0 += k1;  x1 += ks2 + 1u;
    TF_RND(17) TF_RND(29) TF_RND(16) TF_RND(24)  x0 += ks2; x1 += k0 + 2u;
    TF_RND(13) TF_RND(15) TF_RND(26) TF_RND(6)   x0 += k0;  x1 += k1 + 3u;
    TF_RND(17) TF_RND(29) TF_RND(16) TF_RND(24)  x0 += k1;  x1 += ks2 + 4u;
    TF_RND(13) TF_RND(15) TF_RND(26) TF_RND(6)   x0 += ks2; x1 += k0 + 5u;
#undef TF_RND
    o0 = x0; o1 = x1;
}

// start index for batch b (JAX threefry_partitionable=True path):
//   k1,k2 = split(key(42)); bits_b = o0^o1 of tf2x32(k2,(0,b)); start = bits & 16383
__device__ __forceinline__ int jax_start_idx(int b) {
    uint32_t k2a, k2b;
    threefry2x32(0u, 42u, 0u, 1u, k2a, k2b);
    uint32_t o0, o1;
    threefry2x32(k2a, k2b, 0u, (uint32_t)b, o0, o1);
    return (int)((o0 ^ o1) & (uint32_t)(N_PTS - 1));
}

// ---------------- cluster DSMEM / mbarrier helpers ----------------
__device__ __forceinline__ void st_async_peer_v4(uint32_t laddr, uint32_t lmbar,
                                                 uint32_t peer,
                                                 uint32_t a, uint32_t b,
                                                 uint32_t c, uint32_t d) {
    uint32_t ra, rm;
    asm volatile("mapa.shared::cluster.u32 %0, %1, %2;" : "=r"(ra) : "r"(laddr), "r"(peer));
    asm volatile("mapa.shared::cluster.u32 %0, %1, %2;" : "=r"(rm) : "r"(lmbar), "r"(peer));
    asm volatile("st.async.shared::cluster.mbarrier::complete_tx::bytes.v4.b32 "
                 "[%0], {%1,%2,%3,%4}, [%5];"
                 :: "r"(ra), "r"(a), "r"(b), "r"(c), "r"(d), "r"(rm) : "memory");
}
__device__ __forceinline__ void mbar_expect_tx(uint32_t mbar, uint32_t bytes) {
    asm volatile("mbarrier.arrive.expect_tx.shared.b64 _, [%0], %1;"
                 :: "r"(mbar), "r"(bytes) : "memory");
}
__device__ __forceinline__ void mbar_wait(uint32_t mbar, uint32_t phase) {
    uint32_t done = 0;
    while (!done) {
        asm volatile(
            "{\n\t.reg .pred p;\n\t"
            "mbarrier.try_wait.parity.acquire.cluster.shared::cta.b64 p, [%1], %2, 0x989680;\n\t"
            "selp.b32 %0, 1, 0, p;\n\t}"
            : "=r"(done) : "r"(mbar), "r"(phase) : "memory");
    }
}

// ---------------- FPS: one 8-CTA cluster per batch ----------------
// BLOCKED mapping: thread t of CTA rank owns indices
//   [rank*2048 + t*PPT, rank*2048 + t*PPT + PPT)
// so index order == (slot, lane, j) order -> all tie-breaks are ffs(ballot).
__global__ void __cluster_dims__(CL, 1, 1) fps_kernel(const float* __restrict__ xyz,
                                                      float* __restrict__ out_xyz) {
    const int b = blockIdx.x / CL;
    uint32_t rank;
    asm("mov.u32 %0, %%cluster_ctarank;" : "=r"(rank));
    const float* __restrict__ X = xyz + (size_t)b * N_PTS * 3;
    const int t = threadIdx.x;
    const int lane = t & 31, w = t >> 5;
    const int tbase = (int)rank * (TPB * PPT) + t * PPT;

    // register-resident packed point pairs + scalar running min distance
    uint64_t px2[NPAIR], py2[NPAIR], pz2[NPAIR];
    float md[PPT];
#pragma unroll
    for (int p = 0; p < NPAIR; p++) {
        const float* a = X + 3 * (tbase + 2 * p);
        px2[p] = pack2(a[0], a[3]);
        py2[p] = pack2(a[1], a[4]);
        pz2[p] = pack2(a[2], a[5]);
    }
#pragma unroll
    for (int j = 0; j < PPT; j++) md[j] = __int_as_float(0x7f800000);  // +inf

    // cluster-wide candidates: one v4 {dist,x,y,z} per slot, double-buffered
    __shared__ uint4 s_q[2][NSLOT];
    __shared__ unsigned long long s_mbar[2];

    if (t == 0) {
        asm volatile("mbarrier.init.shared.b64 [%0], %1;"
                     :: "r"((uint32_t)__cvta_generic_to_shared(&s_mbar[0])), "r"(1) : "memory");
        asm volatile("mbarrier.init.shared.b64 [%0], %1;"
                     :: "r"((uint32_t)__cvta_generic_to_shared(&s_mbar[1])), "r"(1) : "memory");
    }
    __syncthreads();
    asm volatile("barrier.cluster.arrive.aligned;" ::: "memory");
    asm volatile("barrier.cluster.wait.aligned;" ::: "memory");

    int cur = jax_start_idx(b);
    float qx = X[3 * cur + 0], qy = X[3 * cur + 1], qz = X[3 * cur + 2];

    for (int s = 0; ; s++) {
        if (rank == 0 && t == 0) {
            float* o = out_xyz + ((size_t)b * N_SAMP + s) * 3;
            o[0] = qx; o[1] = qy; o[2] = qz;
        }
        if (s == N_SAMP - 1) break;

        const int buf = s & 1;
        // arm this phase's mbar (arrival count 1 = this arrive.expect_tx, so the
        // phase cannot flip before this post even if producer bytes land first)
        if (t == 0)
            mbar_expect_tx((uint32_t)__cvta_generic_to_shared(&s_mbar[buf]), TX_BYTES);

        // ---- thread-local update + best. EXACT: a-b == a+(-b) (IEEE), f32x2
        //      lanes are per-lane .rn mul/add identical to scalar; left-assoc sum ----
        const uint64_t nqx2 = pack2(-qx, -qx);
        const uint64_t nqy2 = pack2(-qy, -qy);
        const uint64_t nqz2 = pack2(-qz, -qz);
        uint32_t bu = 0u;
        float bx = 0.f, by = 0.f, bz = 0.f;
#pragma unroll
        for (int p = 0; p < NPAIR; p++) {
            uint64_t dx2 = add2(px2[p], nqx2);
            uint64_t dy2 = add2(py2[p], nqy2);
            uint64_t dz2 = add2(pz2[p], nqz2);
            uint64_t d2p = add2(add2(mul2(dx2, dx2), mul2(dy2, dy2)), mul2(dz2, dz2));
            float dlo, dhi;
            unpack2(d2p, dlo, dhi);
            {   // point 2p (lower index first: strict > keeps smallest index)
                float m = fminf(md[2 * p], dlo);
                md[2 * p] = m;
                uint32_t mu = __float_as_uint(m);   // m>=0: IEEE order == u32 order
                if (mu > bu) {
                    bu = mu;
                    float lx, hx, ly, hy, lz, hz;
                    unpack2(px2[p], lx, hx); unpack2(py2[p], ly, hy); unpack2(pz2[p], lz, hz);
                    bx = lx; by = ly; bz = lz;
                }
            }
            {   // point 2p+1
                float m = fminf(md[2 * p + 1], dhi);
                md[2 * p + 1] = m;
                uint32_t mu = __float_as_uint(m);
                if (mu > bu) {
                    bu = mu;
                    float lx, hx, ly, hy, lz, hz;
                    unpack2(px2[p], lx, hx); unpack2(py2[p], ly, hy); unpack2(pz2[p], lz, hz);
                    bx = hx; by = hy; bz = hz;
                }
            }
        }
        // ---- warp argmax: lowest winning lane == smallest index (blocked map) ----
        uint32_t wm = __reduce_max_sync(FULL, bu);
        uint32_t mk = __ballot_sync(FULL, bu == wm);
        int ls = __ffs(mk) - 1;
        uint32_t cx = __shfl_sync(FULL, __float_as_uint(bx), ls);
        uint32_t cy = __shfl_sync(FULL, __float_as_uint(by), ls);
        uint32_t cz = __shfl_sync(FULL, __float_as_uint(bz), ls);
        // lanes 0..7: one fused store+signal of {dist,x,y,z} to peer=lane
        if (lane < CL) {
            uint32_t aq = (uint32_t)__cvta_generic_to_shared(
                              &s_q[buf][(int)rank * NWARP + w]);
            uint32_t mb = (uint32_t)__cvta_generic_to_shared(&s_mbar[buf]);
            st_async_peer_v4(aq, mb, (uint32_t)lane, wm, cx, cy, cz);
        }

        // ---- all warps: wait, then 1-slot-per-lane reduce; lowest winning slot
        //      == smallest index (slot order == index order) ----
        mbar_wait((uint32_t)__cvta_generic_to_shared(&s_mbar[buf]), (uint32_t)((s >> 1) & 1));
        uint4 dv = s_q[buf][lane];
        uint32_t gm = __reduce_max_sync(FULL, dv.x);
        uint32_t mk2 = __ballot_sync(FULL, dv.x == gm);
        int ws = __ffs(mk2) - 1;
        qx = __uint_as_float(__shfl_sync(FULL, dv.y, ws));
        qy = __uint_as_float(__shfl_sync(FULL, dv.z, ws));
        qz = __uint_as_float(__shfl_sync(FULL, dv.w, ws));
    }

    // drain: no CTA exits while peers may still target its smem
    asm volatile("barrier.cluster.arrive.aligned;" ::: "memory");
    asm volatile("barrier.cluster.wait.aligned;" ::: "memory");
}

// ---------------- ball query: one warp per query, first-32-by-index ----------------
__global__ void ball_kernel(const float* __restrict__ xyz,
                            const float* __restrict__ samp) {
    const int warp = (int)((blockIdx.x * blockDim.x + threadIdx.x) >> 5);
    const int lane = threadIdx.x & 31;
    if (warp >= BATCH * N_SAMP) return;
    const int b = warp >> 10;  // 1024 samples per batch
    const float* q = samp + (size_t)warp * 3;
    const float qx = q[0], qy = q[1], qz = q[2];
    const float* __restrict__ X = xyz + (size_t)b * N_PTS * 3;
    int* out = g_nidx + (size_t)warp * K_NEI;

    out[lane] = -1;  // default padding
    int cnt = 0;
    const float R2 = 0.04f;  // f32(0.04): matches JAX weak-typed radius*radius
    for (int base = 0; base < N_PTS && cnt < K_NEI; base += 32) {
        const int i = base + lane;
        float dx = __fsub_rn(qx, X[3 * i + 0]);
        float dy = __fsub_rn(qy, X[3 * i + 1]);
        float dz = __fsub_rn(qz, X[3 * i + 2]);
        float d2 = __fadd_rn(__fadd_rn(__fmul_rn(dx, dx), __fmul_rn(dy, dy)),
                             __fmul_rn(dz, dz));
        const bool in = d2 < R2;
        const unsigned m = __ballot_sync(0xffffffffu, in);
        if (in) {
            int r = cnt + __popc(m & ((1u << lane) - 1u));
            if (r < K_NEI) out[r] = i;
        }
        cnt += __popc(m);
    }
}

// ---------------- gather: one warp per (b,s,k) row, 128 floats ----------------
__global__ void gather_kernel(const float* __restrict__ feat,
                              float* __restrict__ out_feat) {
    const int warp = (int)((blockIdx.x * blockDim.x + threadIdx.x) >> 5);
    const int lane = threadIdx.x & 31;
    if (warp >= BATCH * N_SAMP * K_NEI) return;
    const int b = warp >> 15;  // 1024*32 rows per batch
    int idx = g_nidx[warp];
    int row = (idx < 0) ? N_SAMP : idx;  // -1 -> feat[:, 1024, :]
    const float4* src = (const float4*)(feat + ((size_t)b * N_PTS + row) * C_FEAT);
    float4* dst = (float4*)(out_feat + (size_t)warp * C_FEAT);
    dst[lane] = src[lane];
}

extern "C" void kernel_launch(void* const* d_in, const int* in_sizes, int n_in,
                              void* d_out, int out_size) {
    const float* xyz  = (const float*)d_in[0];
    const float* feat = (const float*)d_in[1];
    if (n_in >= 2 && in_sizes[0] != BATCH * N_PTS * 3) {  // defensive: identify by size
        xyz  = (const float*)d_in[1];
        feat = (const float*)d_in[0];
    }
    float* out = (float*)d_out;
    float* out_feat = out + (size_t)BATCH * N_SAMP * 3;

    fps_kernel<<<BATCH * CL, TPB>>>(xyz, out);

    const int ball_threads = BATCH * N_SAMP * 32;            // one warp/query
    ball_kernel<<<ball_threads / 256, 256>>>(xyz, out);

    const int gath_threads = BATCH * N_SAMP * K_NEI * 32;    // one warp/row
    gather_kernel<<<gath_threads / 256, 256>>>(feat, out_feat);
}

// round 9
// speedup vs baseline: 1.0224x; 1.0224x over previous
#include <cuda_runtime.h>
#include <cstdint>

#define BATCH  4
#define N_PTS  16384
#define N_SAMP 1024
#define K_NEI  32
#define C_FEAT 128
#define CL     8               // cluster size (CTAs per batch)
#define TPB    128
#define NWARP  (TPB / 32)      // 4 warps per CTA
#define PPT    16              // N_PTS / (CL*TPB)
#define NSLOT  (CL * NWARP)    // 32 cluster-wide warp candidates (== warp size)
#define FULL   0xffffffffu
#define TX_BYTES (NSLOT * 16u) // 32 producers x one v4 (16B)

// scratch: neighbor indices (device global -> no allocation)
__device__ int g_nidx[BATCH * N_SAMP * K_NEI];

// ---------------- threefry2x32 (JAX-compatible, both output words) ----------------
__device__ __forceinline__ uint32_t rotl32(uint32_t x, int r) {
    return (x << r) | (x >> (32 - r));
}

__device__ __forceinline__ void threefry2x32(uint32_t k0, uint32_t k1,
                                             uint32_t x0, uint32_t x1,
                                             uint32_t& o0, uint32_t& o1) {
    uint32_t ks2 = k0 ^ k1 ^ 0x1BD11BDAu;
    x0 += k0; x1 += k1;
#define TF_RND(r) { x0 += x1; x1 = rotl32(x1, (r)); x1 ^= x0; }
    TF_RND(13) TF_RND(15) TF_RND(26) TF_RND(6)   x0 += k1;  x1 += ks2 + 1u;
    TF_RND(17) TF_RND(29) TF_RND(16) TF_RND(24)  x0 += ks2; x1 += k0 + 2u;
    TF_RND(13) TF_RND(15) TF_RND(26) TF_RND(6)   x0 += k0;  x1 += k1 + 3u;
    TF_RND(17) TF_RND(29) TF_RND(16) TF_RND(24)  x0 += k1;  x1 += ks2 + 4u;
    TF_RND(13) TF_RND(15) TF_RND(26) TF_RND(6)   x0 += ks2; x1 += k0 + 5u;
#undef TF_RND
    o0 = x0; o1 = x1;
}

// start index for batch b (JAX threefry_partitionable=True path):
//   k1,k2 = split(key(42)); bits_b = o0^o1 of tf2x32(k2,(0,b)); start = bits & 16383
__device__ __forceinline__ int jax_start_idx(int b) {
    uint32_t k2a, k2b;
    threefry2x32(0u, 42u, 0u, 1u, k2a, k2b);
    uint32_t o0, o1;
    threefry2x32(k2a, k2b, 0u, (uint32_t)b, o0, o1);
    return (int)((o0 ^ o1) & (uint32_t)(N_PTS - 1));
}

// ---------------- cluster DSMEM / mbarrier helpers ----------------
__device__ __forceinline__ void st_async_peer_v4(uint32_t laddr, uint32_t lmbar,
                                                 uint32_t peer,
                                                 uint32_t a, uint32_t b,
                                                 uint32_t c, uint32_t d) {
    uint32_t ra, rm;
    asm volatile("mapa.shared::cluster.u32 %0, %1, %2;" : "=r"(ra) : "r"(laddr), "r"(peer));
    asm volatile("mapa.shared::cluster.u32 %0, %1, %2;" : "=r"(rm) : "r"(lmbar), "r"(peer));
    asm volatile("st.async.shared::cluster.mbarrier::complete_tx::bytes.v4.b32 "
                 "[%0], {%1,%2,%3,%4}, [%5];"
                 :: "r"(ra), "r"(a), "r"(b), "r"(c), "r"(d), "r"(rm) : "memory");
}
__device__ __forceinline__ void mbar_expect_tx(uint32_t mbar, uint32_t bytes) {
    asm volatile("mbarrier.arrive.expect_tx.shared.b64 _, [%0], %1;"
                 :: "r"(mbar), "r"(bytes) : "memory");
}
__device__ __forceinline__ void mbar_wait(uint32_t mbar, uint32_t phase) {
    uint32_t done = 0;
    while (!done) {
        asm volatile(
            "{\n\t.reg .pred p;\n\t"
            "mbarrier.try_wait.parity.acquire.cluster.shared::cta.b64 p, [%1], %2, 0x989680;\n\t"
            "selp.b32 %0, 1, 0, p;\n\t}"
            : "=r"(done) : "r"(mbar), "r"(phase) : "memory");
    }
}

// ---------------- FPS: one 8-CTA cluster per batch ----------------
// BLOCKED mapping: thread t of CTA rank owns indices
//   [rank*2048 + t*PPT, rank*2048 + (t+1)*PPT)
// so index order == (slot, lane, j) order -> every tie-break is ffs(ballot),
// and no index ever needs to be reduced or transported.
__global__ void __cluster_dims__(CL, 1, 1) fps_kernel(const float* __restrict__ xyz,
                                                      float* __restrict__ out_xyz) {
    const int b = blockIdx.x / CL;
    uint32_t rank;
    asm("mov.u32 %0, %%cluster_ctarank;" : "=r"(rank));
    const float* __restrict__ X = xyz + (size_t)b * N_PTS * 3;
    const int t = threadIdx.x;
    const int lane = t & 31, w = t >> 5;
    const int tbase = (int)rank * (TPB * PPT) + t * PPT;

    // register-resident points + running min distance (scalar: short dep chains)
    float px[PPT], py[PPT], pz[PPT], md[PPT];
#pragma unroll
    for (int j = 0; j < PPT; j++) {
        const float* a = X + 3 * (tbase + j);
        px[j] = a[0];
        py[j] = a[1];
        pz[j] = a[2];
        md[j] = __int_as_float(0x7f800000);  // +inf
    }

    // cluster-wide candidates: one v4 {dist,x,y,z} per slot, double-buffered
    __shared__ uint4 s_q[2][NSLOT];
    __shared__ unsigned long long s_mbar[2];

    if (t == 0) {
        asm volatile("mbarrier.init.shared.b64 [%0], %1;"
                     :: "r"((uint32_t)__cvta_generic_to_shared(&s_mbar[0])), "r"(1) : "memory");
        asm volatile("mbarrier.init.shared.b64 [%0], %1;"
                     :: "r"((uint32_t)__cvta_generic_to_shared(&s_mbar[1])), "r"(1) : "memory");
    }
    __syncthreads();
    asm volatile("barrier.cluster.arrive.aligned;" ::: "memory");
    asm volatile("barrier.cluster.wait.aligned;" ::: "memory");

    int cur = jax_start_idx(b);
    float qx = X[3 * cur + 0], qy = X[3 * cur + 1], qz = X[3 * cur + 2];

    for (int s = 0; ; s++) {
        if (rank == 0 && t == 0) {
            float* o = out_xyz + ((size_t)b * N_SAMP + s) * 3;
            o[0] = qx; o[1] = qy; o[2] = qz;
        }
        if (s == N_SAMP - 1) break;

        const int buf = s & 1;
        // arm this phase's mbar (arrival count 1 = this arrive.expect_tx, so the
        // phase cannot flip before this post even if producer bytes land first)
        if (t == 0)
            mbar_expect_tx((uint32_t)__cvta_generic_to_shared(&s_mbar[buf]), TX_BYTES);

        // ---- thread-local update + best (EXACT: no FMA, left-assoc sum) ----
        uint32_t bu = 0u;
        float bx = 0.f, by = 0.f, bz = 0.f;
#pragma unroll
        for (int j = 0; j < PPT; j++) {
            float dx = __fsub_rn(px[j], qx);
            float dy = __fsub_rn(py[j], qy);
            float dz = __fsub_rn(pz[j], qz);
            float d2 = __fadd_rn(__fadd_rn(__fmul_rn(dx, dx), __fmul_rn(dy, dy)),
                                 __fmul_rn(dz, dz));
            float m = fminf(md[j], d2);
            md[j] = m;
            uint32_t mu = __float_as_uint(m);  // m >= 0 -> IEEE order == u32 order
            if (mu > bu) {                     // strict >: j asc keeps smallest index
                bu = mu; bx = px[j]; by = py[j]; bz = pz[j];
            }
        }
        // ---- warp argmax: lowest winning lane == smallest index (blocked map) ----
        uint32_t wm = __reduce_max_sync(FULL, bu);
        uint32_t mk = __ballot_sync(FULL, bu == wm);
        int ls = __ffs(mk) - 1;
        uint32_t cx = __shfl_sync(FULL, __float_as_uint(bx), ls);
        uint32_t cy = __shfl_sync(FULL, __float_as_uint(by), ls);
        uint32_t cz = __shfl_sync(FULL, __float_as_uint(bz), ls);
        // lanes 0..7: one fused store+signal of {dist,x,y,z} to peer=lane
        if (lane < CL) {
            uint32_t aq = (uint32_t)__cvta_generic_to_shared(
                              &s_q[buf][(int)rank * NWARP + w]);
            uint32_t mb = (uint32_t)__cvta_generic_to_shared(&s_mbar[buf]);
            st_async_peer_v4(aq, mb, (uint32_t)lane, wm, cx, cy, cz);
        }

        // ---- all warps: wait, 1 slot/lane; lowest winning slot == smallest index ----
        mbar_wait((uint32_t)__cvta_generic_to_shared(&s_mbar[buf]), (uint32_t)((s >> 1) & 1));
        uint4 dv = s_q[buf][lane];
        uint32_t gm = __reduce_max_sync(FULL, dv.x);
        uint32_t mk2 = __ballot_sync(FULL, dv.x == gm);
        int ws = __ffs(mk2) - 1;
        qx = __uint_as_float(__shfl_sync(FULL, dv.y, ws));
        qy = __uint_as_float(__shfl_sync(FULL, dv.z, ws));
        qz = __uint_as_float(__shfl_sync(FULL, dv.w, ws));
    }

    // drain: no CTA exits while peers may still target its smem
    asm volatile("barrier.cluster.arrive.aligned;" ::: "memory");
    asm volatile("barrier.cluster.wait.aligned;" ::: "memory");
}

// ---------------- ball query: one warp per query, first-32-by-index ----------------
__global__ void ball_kernel(const float* __restrict__ xyz,
                            const float* __restrict__ samp) {
    const int warp = (int)((blockIdx.x * blockDim.x + threadIdx.x) >> 5);
    const int lane = threadIdx.x & 31;
    if (warp >= BATCH * N_SAMP) return;
    const int b = warp >> 10;  // 1024 samples per batch
    const float* q = samp + (size_t)warp * 3;
    const float qx = q[0], qy = q[1], qz = q[2];
    const float* __restrict__ X = xyz + (size_t)b * N_PTS * 3;
    int* out = g_nidx + (size_t)warp * K_NEI;

    out[lane] = -1;  // default padding
    int cnt = 0;
    const float R2 = 0.04f;  // f32(0.04): matches JAX weak-typed radius*radius
    for (int base = 0; base < N_PTS && cnt < K_NEI; base += 32) {
        const int i = base + lane;
        float dx = __fsub_rn(qx, X[3 * i + 0]);
        float dy = __fsub_rn(qy, X[3 * i + 1]);
        float dz = __fsub_rn(qz, X[3 * i + 2]);
        float d2 = __fadd_rn(__fadd_rn(__fmul_rn(dx, dx), __fmul_rn(dy, dy)),
                             __fmul_rn(dz, dz));
        const bool in = d2 < R2;
        const unsigned m = __ballot_sync(0xffffffffu, in);
        if (in) {
            int r = cnt + __popc(m & ((1u << lane) - 1u));
            if (r < K_NEI) out[r] = i;
        }
        cnt += __popc(m);
    }
}

// ---------------- gather: one warp per (b,s,k) row, 128 floats ----------------
__global__ void gather_kernel(const float* __restrict__ feat,
                              float* __restrict__ out_feat) {
    const int warp = (int)((blockIdx.x * blockDim.x + threadIdx.x) >> 5);
    const int lane = threadIdx.x & 31;
    if (warp >= BATCH * N_SAMP * K_NEI) return;
    const int b = warp >> 15;  // 1024*32 rows per batch
    int idx = g_nidx[warp];
    int row = (idx < 0) ? N_SAMP : idx;  // -1 -> feat[:, 1024, :]
    const float4* src = (const float4*)(feat + ((size_t)b * N_PTS + row) * C_FEAT);
    float4* dst = (float4*)(out_feat + (size_t)warp * C_FEAT);
    dst[lane] = src[lane];
}

extern "C" void kernel_launch(void* const* d_in, const int* in_sizes, int n_in,
                              void* d_out, int out_size) {
    const float* xyz  = (const float*)d_in[0];
    const float* feat = (const float*)d_in[1];
    if (n_in >= 2 && in_sizes[0] != BATCH * N_PTS * 3) {  // defensive: identify by size
        xyz  = (const float*)d_in[1];
        feat = (const float*)d_in[0];
    }
    float* out = (float*)d_out;
    float* out_feat = out + (size_t)BATCH * N_SAMP * 3;

    fps_kernel<<<BATCH * CL, TPB>>>(xyz, out);

    const int ball_threads = BATCH * N_SAMP * 32;            // one warp/query
    ball_kernel<<<ball_threads / 256, 256>>>(xyz, out);

    const int gath_threads = BATCH * N_SAMP * K_NEI * 32;    // one warp/row
    gather_kernel<<<gath_threads / 256, 256>>>(feat, out_feat);
}

// round 10
// speedup vs baseline: 1.1777x; 1.1520x over previous
#include <cuda_runtime.h>
#include <cstdint>

#define BATCH  4
#define N_PTS  16384
#define N_SAMP 1024
#define K_NEI  32
#define C_FEAT 128
#define CL     8               // cluster size (CTAs per batch)
#define TPB    128
#define NWARP  (TPB / 32)      // 4 warps per CTA
#define PPT    16              // N_PTS / (CL*TPB)
#define NSLOT  (CL * NWARP)    // 32 cluster-wide warp candidates (== warp size)
#define FULL   0xffffffffu
#define TX_BYTES (NSLOT * 16u) // 32 producers x one v4 (16B)

// scratch: neighbor indices (device global -> no allocation)
__device__ int g_nidx[BATCH * N_SAMP * K_NEI];

// ---------------- threefry2x32 (JAX-compatible, both output words) ----------------
__device__ __forceinline__ uint32_t rotl32(uint32_t x, int r) {
    return (x << r) | (x >> (32 - r));
}

__device__ __forceinline__ void threefry2x32(uint32_t k0, uint32_t k1,
                                             uint32_t x0, uint32_t x1,
                                             uint32_t& o0, uint32_t& o1) {
    uint32_t ks2 = k0 ^ k1 ^ 0x1BD11BDAu;
    x0 += k0; x1 += k1;
#define TF_RND(r) { x0 += x1; x1 = rotl32(x1, (r)); x1 ^= x0; }
    TF_RND(13) TF_RND(15) TF_RND(26) TF_RND(6)   x0 += k1;  x1 += ks2 + 1u;
    TF_RND(17) TF_RND(29) TF_RND(16) TF_RND(24)  x0 += ks2; x1 += k0 + 2u;
    TF_RND(13) TF_RND(15) TF_RND(26) TF_RND(6)   x0 += k0;  x1 += k1 + 3u;
    TF_RND(17) TF_RND(29) TF_RND(16) TF_RND(24)  x0 += k1;  x1 += ks2 + 4u;
    TF_RND(13) TF_RND(15) TF_RND(26) TF_RND(6)   x0 += ks2; x1 += k0 + 5u;
#undef TF_RND
    o0 = x0; o1 = x1;
}

// start index for batch b (JAX threefry_partitionable=True path):
//   k1,k2 = split(key(42)); bits_b = o0^o1 of tf2x32(k2,(0,b)); start = bits & 16383
__device__ __forceinline__ int jax_start_idx(int b) {
    uint32_t k2a, k2b;
    threefry2x32(0u, 42u, 0u, 1u, k2a, k2b);
    uint32_t o0, o1;
    threefry2x32(k2a, k2b, 0u, (uint32_t)b, o0, o1);
    return (int)((o0 ^ o1) & (uint32_t)(N_PTS - 1));
}

// ---------------- cluster DSMEM / mbarrier helpers ----------------
__device__ __forceinline__ uint32_t mapa_peer(uint32_t laddr, uint32_t peer) {
    uint32_t r;
    asm volatile("mapa.shared::cluster.u32 %0, %1, %2;" : "=r"(r) : "r"(laddr), "r"(peer));
    return r;
}
// fused store+signal with pre-resolved remote addresses
__device__ __forceinline__ void st_async_raw_v4(uint32_t raddr, uint32_t rmbar,
                                                uint32_t a, uint32_t b,
                                                uint32_t c, uint32_t d) {
    asm volatile("st.async.shared::cluster.mbarrier::complete_tx::bytes.v4.b32 "
                 "[%0], {%1,%2,%3,%4}, [%5];"
                 :: "r"(raddr), "r"(a), "r"(b), "r"(c), "r"(d), "r"(rmbar) : "memory");
}
__device__ __forceinline__ void mbar_expect_tx(uint32_t mbar, uint32_t bytes) {
    asm volatile("mbarrier.arrive.expect_tx.shared.b64 _, [%0], %1;"
                 :: "r"(mbar), "r"(bytes) : "memory");
}
__device__ __forceinline__ void mbar_wait(uint32_t mbar, uint32_t phase) {
    uint32_t done = 0;
    while (!done) {
        asm volatile(
            "{\n\t.reg .pred p;\n\t"
            "mbarrier.try_wait.parity.acquire.cluster.shared::cta.b64 p, [%1], %2, 0x989680;\n\t"
            "selp.b32 %0, 1, 0, p;\n\t}"
            : "=r"(done) : "r"(mbar), "r"(phase) : "memory");
    }
}

// ---------------- FPS: one 8-CTA cluster per batch ----------------
// BLOCKED mapping: thread t of CTA rank owns indices
//   [rank*2048 + t*PPT, rank*2048 + (t+1)*PPT)
// so index order == (slot, lane, j) order -> every tie-break is ffs(ballot),
// and no index ever needs to be reduced or transported.
__global__ void __cluster_dims__(CL, 1, 1) __launch_bounds__(TPB, 1)
fps_kernel(const float* __restrict__ xyz, float* __restrict__ out_xyz) {
    const int b = blockIdx.x / CL;
    uint32_t rank;
    asm("mov.u32 %0, %%cluster_ctarank;" : "=r"(rank));
    const float* __restrict__ X = xyz + (size_t)b * N_PTS * 3;
    const int t = threadIdx.x;
    const int lane = t & 31, w = t >> 5;
    const int tbase = (int)rank * (TPB * PPT) + t * PPT;

    // register-resident points + running min distance
    float px[PPT], py[PPT], pz[PPT], md[PPT];
#pragma unroll
    for (int j = 0; j < PPT; j++) {
        const float* a = X + 3 * (tbase + j);
        px[j] = a[0];
        py[j] = a[1];
        pz[j] = a[2];
        md[j] = __int_as_float(0x7f800000);  // +inf
    }

    // cluster-wide candidates: one v4 {dist,x,y,z} per slot, double-buffered
    __shared__ uint4 s_q[2][NSLOT];
    __shared__ unsigned long long s_mbar[2];

    if (t == 0) {
        asm volatile("mbarrier.init.shared.b64 [%0], %1;"
                     :: "r"((uint32_t)__cvta_generic_to_shared(&s_mbar[0])), "r"(1) : "memory");
        asm volatile("mbarrier.init.shared.b64 [%0], %1;"
                     :: "r"((uint32_t)__cvta_generic_to_shared(&s_mbar[1])), "r"(1) : "memory");
    }
    __syncthreads();
    asm volatile("barrier.cluster.arrive.aligned;" ::: "memory");
    asm volatile("barrier.cluster.wait.aligned;" ::: "memory");

    // pre-resolve remote slot/mbar addresses for my warp's slot, both buffers
    const int myslot = (int)rank * NWARP + w;
    uint32_t rs0[CL], rs1[CL], rm0[CL], rm1[CL];
    {
        uint32_t a0 = (uint32_t)__cvta_generic_to_shared(&s_q[0][myslot]);
        uint32_t a1 = (uint32_t)__cvta_generic_to_shared(&s_q[1][myslot]);
        uint32_t m0 = (uint32_t)__cvta_generic_to_shared(&s_mbar[0]);
        uint32_t m1 = (uint32_t)__cvta_generic_to_shared(&s_mbar[1]);
#pragma unroll
        for (int p = 0; p < CL; p++) {
            rs0[p] = mapa_peer(a0, (uint32_t)p);
            rs1[p] = mapa_peer(a1, (uint32_t)p);
            rm0[p] = mapa_peer(m0, (uint32_t)p);
            rm1[p] = mapa_peer(m1, (uint32_t)p);
        }
    }

    int cur = jax_start_idx(b);
    float qx = X[3 * cur + 0], qy = X[3 * cur + 1], qz = X[3 * cur + 2];

    for (int s = 0; ; s++) {
        if (rank == 0 && t == 0) {
            float* o = out_xyz + ((size_t)b * N_SAMP + s) * 3;
            o[0] = qx; o[1] = qy; o[2] = qz;
        }
        if (s == N_SAMP - 1) break;

        const int buf = s & 1;
        // arm this phase's mbar (arrival count 1 = this arrive.expect_tx, so the
        // phase cannot flip before this post even if producer bytes land first)
        if (t == 0)
            mbar_expect_tx((uint32_t)__cvta_generic_to_shared(&s_mbar[buf]), TX_BYTES);

        // ---- thread-local update: all 16 distances independent (full ILP).
        //      EXACT: no FMA contraction, left-assoc sum, IEEE fminf ----
        float m[PPT];
#pragma unroll
        for (int j = 0; j < PPT; j++) {
            float dx = __fsub_rn(px[j], qx);
            float dy = __fsub_rn(py[j], qy);
            float dz = __fsub_rn(pz[j], qz);
            float d2 = __fadd_rn(__fadd_rn(__fmul_rn(dx, dx), __fmul_rn(dy, dy)),
                                 __fmul_rn(dz, dz));
            float mm = fminf(md[j], d2);
            md[j] = mm;
            m[j] = mm;
        }
        // ---- depth-4 adjacent-pair argmax tree (left-priority => smallest j
        //      on ties, i.e. exact argmax-first). values finite non-negative. ----
        float tv[8], tx[8], ty[8], tz[8];
#pragma unroll
        for (int k = 0; k < 8; k++) {
            bool g = m[2 * k + 1] > m[2 * k];
            tv[k] = g ? m[2 * k + 1]  : m[2 * k];
            tx[k] = g ? px[2 * k + 1] : px[2 * k];
            ty[k] = g ? py[2 * k + 1] : py[2 * k];
            tz[k] = g ? pz[2 * k + 1] : pz[2 * k];
        }
#pragma unroll
        for (int n = 4; n >= 1; n >>= 1) {
#pragma unroll
            for (int k = 0; k < n; k++) {
                bool g = tv[2 * k + 1] > tv[2 * k];
                tv[k] = g ? tv[2 * k + 1] : tv[2 * k];
                tx[k] = g ? tx[2 * k + 1] : tx[2 * k];
                ty[k] = g ? ty[2 * k + 1] : ty[2 * k];
                tz[k] = g ? tz[2 * k + 1] : tz[2 * k];
            }
        }
        const uint32_t bu = __float_as_uint(tv[0]);  // >=0: IEEE order == u32 order

        // ---- warp argmax; winning lane (lowest on ties == smallest index)
        //      broadcasts its own candidate to all 8 CTAs directly ----
        uint32_t wm = __reduce_max_sync(FULL, bu);
        uint32_t mk = __ballot_sync(FULL, bu == wm);
        if (lane == __ffs(mk) - 1) {
            uint32_t cx = __float_as_uint(tx[0]);
            uint32_t cy = __float_as_uint(ty[0]);
            uint32_t cz = __float_as_uint(tz[0]);
            if (buf) {
#pragma unroll
                for (int p = 0; p < CL; p++)
                    st_async_raw_v4(rs1[p], rm1[p], wm, cx, cy, cz);
            } else {
#pragma unroll
                for (int p = 0; p < CL; p++)
                    st_async_raw_v4(rs0[p], rm0[p], wm, cx, cy, cz);
            }
        }

        // ---- all warps: wait, 1 slot/lane; lowest winning slot == smallest index ----
        mbar_wait((uint32_t)__cvta_generic_to_shared(&s_mbar[buf]), (uint32_t)((s >> 1) & 1));
        uint4 dv = s_q[buf][lane];
        uint32_t gm = __reduce_max_sync(FULL, dv.x);
        uint32_t mk2 = __ballot_sync(FULL, dv.x == gm);
        int ws = __ffs(mk2) - 1;
        qx = __uint_as_float(__shfl_sync(FULL, dv.y, ws));
        qy = __uint_as_float(__shfl_sync(FULL, dv.z, ws));
        qz = __uint_as_float(__shfl_sync(FULL, dv.w, ws));
    }

    // drain: no CTA exits while peers may still target its smem
    asm volatile("barrier.cluster.arrive.aligned;" ::: "memory");
    asm volatile("barrier.cluster.wait.aligned;" ::: "memory");
}

// ---------------- ball query: one warp per query, first-32-by-index ----------------
__global__ void ball_kernel(const float* __restrict__ xyz,
                            const float* __restrict__ samp) {
    const int warp = (int)((blockIdx.x * blockDim.x + threadIdx.x) >> 5);
    const int lane = threadIdx.x & 31;
    if (warp >= BATCH * N_SAMP) return;
    const int b = warp >> 10;  // 1024 samples per batch
    const float* q = samp + (size_t)warp * 3;
    const float qx = q[0], qy = q[1], qz = q[2];
    const float* __restrict__ X = xyz + (size_t)b * N_PTS * 3;
    int* out = g_nidx + (size_t)warp * K_NEI;

    out[lane] = -1;  // default padding
    int cnt = 0;
    const float R2 = 0.04f;  // f32(0.04): matches JAX weak-typed radius*radius
    for (int base = 0; base < N_PTS && cnt < K_NEI; base += 32) {
        const int i = base + lane;
        float dx = __fsub_rn(qx, X[3 * i + 0]);
        float dy = __fsub_rn(qy, X[3 * i + 1]);
        float dz = __fsub_rn(qz, X[3 * i + 2]);
        float d2 = __fadd_rn(__fadd_rn(__fmul_rn(dx, dx), __fmul_rn(dy, dy)),
                             __fmul_rn(dz, dz));
        const bool in = d2 < R2;
        const unsigned m = __ballot_sync(0xffffffffu, in);
        if (in) {
            int r = cnt + __popc(m & ((1u << lane) - 1u));
            if (r < K_NEI) out[r] = i;
        }
        cnt += __popc(m);
    }
}

// ---------------- gather: one warp per (b,s,k) row, 128 floats ----------------
__global__ void gather_kernel(const float* __restrict__ feat,
                              float* __restrict__ out_feat) {
    const int warp = (int)((blockIdx.x * blockDim.x + threadIdx.x) >> 5);
    const int lane = threadIdx.x & 31;
    if (warp >= BATCH * N_SAMP * K_NEI) return;
    const int b = warp >> 15;  // 1024*32 rows per batch
    int idx = g_nidx[warp];
    int row = (idx < 0) ? N_SAMP : idx;  // -1 -> feat[:, 1024, :]
    const float4* src = (const float4*)(feat + ((size_t)b * N_PTS + row) * C_FEAT);
    float4* dst = (float4*)(out_feat + (size_t)warp * C_FEAT);
    dst[lane] = src[lane];
}

extern "C" void kernel_launch(void* const* d_in, const int* in_sizes, int n_in,
                              void* d_out, int out_size) {
    const float* xyz  = (const float*)d_in[0];
    const float* feat = (const float*)d_in[1];
    if (n_in >= 2 && in_sizes[0] != BATCH * N_PTS * 3) {  // defensive: identify by size
        xyz  = (const float*)d_in[1];
        feat = (const float*)d_in[0];
    }
    float* out = (float*)d_out;
    float* out_feat = out + (size_t)BATCH * N_SAMP * 3;

    fps_kernel<<<BATCH * CL, TPB>>>(xyz, out);

    const int ball_threads = BATCH * N_SAMP * 32;            // one warp/query
    ball_kernel<<<ball_threads / 256, 256>>>(xyz, out);

    const int gath_threads = BATCH * N_SAMP * K_NEI * 32;    // one warp/row
    gather_kernel<<<gath_threads / 256, 256>>>(feat, out_feat);
}